// round 4
// baseline (speedup 1.0000x reference)
#include <cuda_runtime.h>
#include <cstddef>

// ---------------- problem constants ----------------
#define H       512
#define IDIM    128
#define KIN     640          // H + I
#define SEQ     256
#define OUTLEN  64
#define CDIM    64
#define BATCH   32
#define NSTEPS  (SEQ + OUTLEN)

// ---------------- partition ----------------
#define GROUPS  4                  // batch groups
#define PCOLS   32                 // column CTAs per group
#define BG      (BATCH / GROUPS)   // 8 batch rows per group
#define COLS    (H / PCOLS)        // 16 hidden cols per CTA
#define OUTC    (CDIM / PCOLS)     // 2 output cols per CTA
#define NCTAS   (GROUPS * PCOLS)   // 128
#define TPB     256
#define RINGD   32                 // ring depth (power of two >= 17)

// padded SMEM strides (floats) — multiples of 4 so double2/float4 stay 16B aligned
#define WS_IN   644          // KIN + 4
#define WS_H    516          // H + 4

// scratch for split-K partials (padded strides -> conflict-free)
#define SCR_FLOATS 4352      // max(128*33, 256*17)

// ---------------- SMEM layout (floats) ----------------
#define OFF_WIN    0
#define OFF_WPASS  (OFF_WIN   + COLS * WS_IN)
#define OFF_WTAU   (OFF_WPASS + COLS * WS_H)
#define OFF_WMEM   (OFF_WTAU  + COLS * WS_H)
#define OFF_WOUT   (OFF_WMEM  + COLS * WS_H)
#define OFF_BIAS   (OFF_WOUT  + OUTC * WS_H)      // 80 floats bias/len block
#define OFF_HS     (OFF_BIAS  + 80)               // BG * KIN staging
#define OFF_TH     (OFF_HS    + BG * KIN)         // 128 (mixed h)
#define OFF_THPRE  (OFF_TH    + 128)              // 128 (pre-mix h)
#define OFF_GT     (OFF_THPRE + 128)              // 128 (tau)
#define OFF_GM     (OFF_GT    + 128)              // 128 (mem gate)
#define OFF_SCR    (OFF_GM    + 128)              // SCR_FLOATS
#define OFF_RING   (OFF_SCR   + SCR_FLOATS)       // RINGD * 128
#define SMEM_FLOATS (OFF_RING + RINGD * 128)
#define SMEM_BYTES  (SMEM_FLOATS * 4)             // ~201 KB < 227 KB

// ---------------- global staging + barriers ----------------
__device__ __align__(16) float g_h0  [GROUPS][BG * H];
__device__ __align__(16) float g_hpre[GROUPS][BG * H];
__device__ __align__(16) float g_hmix[GROUPS][BG * H];

struct __align__(128) GroupBar { unsigned count; unsigned sense; unsigned pad[30]; };
__device__ GroupBar g_bar[GROUPS];

__device__ __forceinline__ float sigf(float z) { return 1.f / (1.f + __expf(-z)); }

// packed dual-FMA: acc(2xf32) += h(2xf32) * w(2xf32); operands loaded as double2
// (LDS.128 -> two 64b regs, no repacking MOVs).
__device__ __forceinline__ void fma2pk(unsigned long long& acc, double h, double w)
{
    asm("fma.rn.f32x2 %0, %1, %2, %0;"
        : "+l"(acc)
        : "l"(__double_as_longlong(h)), "l"(__double_as_longlong(w)));
}

__device__ __forceinline__ float pk_sum(unsigned long long a)
{
    float lo = __uint_as_float((unsigned)(a & 0xffffffffu));
    float hi = __uint_as_float((unsigned)(a >> 32));
    return lo + hi;
}

// 4x4 register tile, one 16B k-chunk of both operands
__device__ __forceinline__ void fma16x2(const double2 hd[4], const double2 wd[4],
                                        unsigned long long acc[4][4])
{
#pragma unroll
    for (int r = 0; r < 4; ++r)
#pragma unroll
        for (int c = 0; c < 4; ++c) {
            fma2pk(acc[r][c], hd[r].x, wd[c].x);
            fma2pk(acc[r][c], hd[r].y, wd[c].y);
        }
}

// Inter-CTA group barrier (32 CTAs, sense-reversing, replay-safe).
// Only tid<128 write global data each phase, so only they fence.
#define GROUP_BAR()                                                          \
    do {                                                                     \
        if (tid < 128) __threadfence();                                      \
        __syncthreads();                                                     \
        if (tid == 0) {                                                      \
            unsigned ns = bsense ^ 1u;                                       \
            bsense = ns;                                                     \
            if (atomicAdd(&g_bar[g].count, 1u) == (unsigned)(PCOLS - 1)) {   \
                g_bar[g].count = 0u;                                         \
                __threadfence();                                             \
                atomicExch(&g_bar[g].sense, ns);                             \
            } else {                                                         \
                while (*(volatile unsigned*)&g_bar[g].sense != ns) { }       \
            }                                                                \
            __threadfence();                                                 \
        }                                                                    \
        __syncthreads();                                                     \
    } while (0)

extern "C" __global__ void __launch_bounds__(TPB, 1)
delay_rnn_kernel(const float* __restrict__ x,       // [B, S, I]
                 const int*   __restrict__ lengths, // [B]
                 const float* __restrict__ W_in,    // [KIN, H]
                 const float* __restrict__ b_in,    // [H]
                 const float* __restrict__ W_pass,  // [H, H]
                 const float* __restrict__ b_pass,
                 const float* __restrict__ W_tau,
                 const float* __restrict__ b_tau,
                 const float* __restrict__ W_mem,
                 const float* __restrict__ b_mem,
                 const float* __restrict__ W_out,   // [H, C]
                 const float* __restrict__ b_out,   // [C]
                 float*       __restrict__ out)     // [B, OUTLEN, C]
{
    extern __shared__ float sm[];
    const int tid     = threadIdx.x;
    const int cta     = blockIdx.x;
    const int g       = cta >> 5;        // batch group
    const int p       = cta & 31;        // column partition
    const int b0      = g * BG;
    const int colbase = p * COLS;
    const int oc0     = p * OUTC;

    float* sWin   = sm + OFF_WIN;
    float* sWpass = sm + OFF_WPASS;
    float* sWtau  = sm + OFF_WTAU;
    float* sWmem  = sm + OFF_WMEM;
    float* sWout  = sm + OFF_WOUT;
    float* sbin   = sm + OFF_BIAS;        // 16
    float* sbpass = sbin + 16;            // 16
    float* sbtau  = sbpass + 16;          // 16
    float* sbmem  = sbtau + 16;           // 16
    float* sbout  = sbmem + 16;           // 4 (2 used)
    int*   slen   = (int*)(sbout + 4);    // 8
    float* h_s    = sm + OFF_HS;
    float* t_h    = sm + OFF_TH;
    float* t_hpre = sm + OFF_THPRE;
    float* g_t    = sm + OFF_GT;
    float* g_m    = sm + OFF_GM;
    float* scr    = sm + OFF_SCR;
    float* ring   = sm + OFF_RING;

    // ---- prologue: weights -> SMEM (transposed, padded) ----
    for (int idx = tid; idx < KIN * COLS; idx += TPB) {
        int k = idx >> 4, cl = idx & 15;
        sWin[cl * WS_IN + k] = W_in[k * H + colbase + cl];
    }
    for (int idx = tid; idx < H * COLS; idx += TPB) {
        int k = idx >> 4, cl = idx & 15;
        sWpass[cl * WS_H + k] = W_pass[k * H + colbase + cl];
        sWtau [cl * WS_H + k] = W_tau [k * H + colbase + cl];
        sWmem [cl * WS_H + k] = W_mem [k * H + colbase + cl];
    }
    for (int idx = tid; idx < H * OUTC; idx += TPB) {
        int k = idx >> 1, c = idx & 1;
        sWout[c * WS_H + k] = W_out[k * CDIM + oc0 + c];
    }
    if (tid < 16) {
        sbin[tid]   = b_in  [colbase + tid];
        sbpass[tid] = b_pass[colbase + tid];
        sbtau[tid]  = b_tau [colbase + tid];
        sbmem[tid]  = b_mem [colbase + tid];
    }
    if (tid < OUTC) sbout[tid] = b_out[oc0 + tid];
    if (tid < BG)   slen[tid]  = lengths[b0 + tid];
    for (int idx = tid; idx < RINGD * 128; idx += TPB) ring[idx] = 0.f;
    if (tid < 128) {  // initial h0 = 0
        int row = tid >> 4, cl = tid & 15;
        g_h0[g][row * H + colbase + cl] = 0.f;
    }

    unsigned bsense = 0;
    if (tid == 0) bsense = *(volatile unsigned*)&g_bar[g].sense;

    GROUP_BAR();   // weights loaded + initial h0 staged everywhere

    // tile coordinates (fixed per thread)
    const int sA  = tid & 31;             // split id, phases A/B (32-way)
    const int tlA = tid >> 5;             // tile id,  phases A/B (8 tiles)
    const int rA  = (tlA & 1) * 4;        // row base 0/4
    const int cA  = (tlA >> 1) * 4;       // col base 0/4/8/12

    const int sC  = tid & 15;             // split id, phase C (16-way)
    const int tlC = tid >> 4;             // tile id,  phase C (16 tiles)
    const int rC  = (tlC & 1) * 4;
    const int cC  = (tlC >> 1) * 4;       // col base 0..28 (32 logical cols)

    // paired-reduction coords (phases A/B): two threads per output element
    const int oR   = tid >> 1;            // output id 0..127
    const int hR   = tid & 1;             // half id
    const int rowR = oR >> 4, clR = oR & 15;

    for (int st = 0; st < NSTEPS; ++st) {
        const bool enc = (st < SEQ);
        const int  Kt  = enc ? KIN : H;

        // ================= Phase A: h_pre = [h0, x_t] @ W_in + b_in =================
        {
            for (int i = tid; i < (BG * H) / 4; i += TPB) {
                int row = i >> 7, kq = i & 127;
                float4 v = __ldcg((const float4*)g_h0[g] + i);
                *((float4*)(h_s + row * KIN) + kq) = v;
            }
            if (enc) {
                int row = tid >> 5, iq = tid & 31;  // 8 rows x 32 f4
                float4 v = __ldg((const float4*)(x + ((size_t)(b0 + row) * SEQ + st) * IDIM) + iq);
                *((float4*)(h_s + row * KIN + H) + iq) = v;
            }
            __syncthreads();

            unsigned long long acc[4][4] = {};
            const int nj = Kt >> 7;                  // 5 (enc) or 4 (dec)
            for (int j = 0; j < nj; ++j) {
                const int k = sA * 4 + j * 128;      // strided split-K, contiguous per warp
                double2 hd[4], wd[4];
#pragma unroll
                for (int r = 0; r < 4; ++r)
                    hd[r] = *(const double2*)(h_s + (rA + r) * KIN + k);
#pragma unroll
                for (int c = 0; c < 4; ++c)
                    wd[c] = *(const double2*)(sWin + (cA + c) * WS_IN + k);
                fma16x2(hd, wd, acc);
            }
#pragma unroll
            for (int r = 0; r < 4; ++r)
#pragma unroll
                for (int c = 0; c < 4; ++c)
                    scr[((rA + r) * 16 + cA + c) * 33 + sA] = pk_sum(acc[r][c]);
            __syncthreads();

            {   // paired reduction: 256 threads, 16 partials each + shfl combine
                float v = 0.f;
#pragma unroll
                for (int s2 = 0; s2 < 16; ++s2) v += scr[oR * 33 + hR * 16 + s2];
                v += __shfl_xor_sync(0xffffffffu, v, 1);
                if (hR == 0) {
                    float hv = v + sbin[clR];
                    t_hpre[oR] = hv;
                    g_hpre[g][rowR * H + colbase + clR] = hv;
                }
            }
        }
        if (!enc) {
            // decode output: out = h0 @ W_out + b_out   (16-way split-K, h0 in h_s)
            __syncthreads();
            const int oo = tid >> 4, kp = tid & 15;     // oo: 8 rows x 2 cols
            const int row = oo >> 1, c = oo & 1;
            const float* hr = h_s + row * KIN + kp * 32;
            const float* wr = sWout + c * WS_H + kp * 32;
            float a = 0.f;
#pragma unroll
            for (int k = 0; k < 32; k += 4) {
                float4 h4 = *(const float4*)(hr + k);
                float4 w4 = *(const float4*)(wr + k);
                a = fmaf(h4.x, w4.x, a); a = fmaf(h4.y, w4.y, a);
                a = fmaf(h4.z, w4.z, a); a = fmaf(h4.w, w4.w, a);
            }
            scr[tid] = a;
            __syncthreads();
            if (tid < 16) {
                float s = 0.f;
#pragma unroll
                for (int j = 0; j < 16; ++j) s += scr[tid * 16 + j];
                const int row2 = tid >> 1, c2 = tid & 1;
                const int td = st - SEQ;
                out[((size_t)(b0 + row2) * OUTLEN + td) * CDIM + oc0 + c2] = s + sbout[c2];
            }
        }
        GROUP_BAR();

        // ====== Phase B: p = h_pre @ W_pass + b_pass;  h = m*p + (1-m)*h_pre ======
        {
            for (int i = tid; i < (BG * H) / 4; i += TPB) {
                int row = i >> 7, kq = i & 127;
                *((float4*)(h_s + row * KIN) + kq) = __ldcg((const float4*)g_hpre[g] + i);
            }
            __syncthreads();

            unsigned long long acc[4][4] = {};
#pragma unroll
            for (int j = 0; j < 4; ++j) {
                const int k = sA * 4 + j * 128;
                double2 hd[4], wd[4];
#pragma unroll
                for (int r = 0; r < 4; ++r)
                    hd[r] = *(const double2*)(h_s + (rA + r) * KIN + k);
#pragma unroll
                for (int c = 0; c < 4; ++c)
                    wd[c] = *(const double2*)(sWpass + (cA + c) * WS_H + k);
                fma16x2(hd, wd, acc);
            }
#pragma unroll
            for (int r = 0; r < 4; ++r)
#pragma unroll
                for (int c = 0; c < 4; ++c)
                    scr[((rA + r) * 16 + cA + c) * 33 + sA] = pk_sum(acc[r][c]);
            __syncthreads();

            {   // paired reduction + mask mixing
                float v = 0.f;
#pragma unroll
                for (int s2 = 0; s2 < 16; ++s2) v += scr[oR * 33 + hR * 16 + s2];
                v += __shfl_xor_sync(0xffffffffu, v, 1);
                if (hR == 0) {
                    float pv = v + sbpass[clR];
                    float hv;
                    if (enc) {
                        float m = (st < slen[rowR]) ? 1.f : 0.f;
                        hv = m * pv + (1.f - m) * t_hpre[oR];
                    } else {
                        hv = pv;
                    }
                    t_h[oR] = hv;
                    g_hmix[g][rowR * H + colbase + clR] = hv;
                }
            }
        }
        GROUP_BAR();

        // ====== Phase C: fused tau/mem gates (8 x 32 outputs) + ring update ======
        {
            for (int i = tid; i < (BG * H) / 4; i += TPB) {
                int row = i >> 7, kq = i & 127;
                *((float4*)(h_s + row * KIN) + kq) = __ldcg((const float4*)g_hmix[g] + i);
            }
            __syncthreads();

            unsigned long long acc[4][4] = {};
#pragma unroll
            for (int j = 0; j < 8; ++j) {
                const int k = sC * 4 + j * 64;
                double2 hd[4], wd[4];
#pragma unroll
                for (int r = 0; r < 4; ++r)
                    hd[r] = *(const double2*)(h_s + (rC + r) * KIN + k);
#pragma unroll
                for (int c = 0; c < 4; ++c) {
                    const int lc = cC + c;    // 0..31 (tile stays on one side)
                    const float* wb = (lc < 16) ? (sWtau + lc * WS_H)
                                                : (sWmem + (lc - 16) * WS_H);
                    wd[c] = *(const double2*)(wb + k);
                }
                fma16x2(hd, wd, acc);
            }
#pragma unroll
            for (int r = 0; r < 4; ++r)
#pragma unroll
                for (int c = 0; c < 4; ++c)
                    scr[((rC + r) * 32 + cC + c) * 17 + sC] = pk_sum(acc[r][c]);
            __syncthreads();

            {   // reduction + gate nonlinearity (all 256 threads, one output each)
                const int row = tid >> 5, lc = tid & 31;
                float v = 0.f;
#pragma unroll 8
                for (int s2 = 0; s2 < 16; ++s2) v += scr[tid * 17 + s2];
                if (lc < 16) {
                    v += sbtau[lc];
                    g_t[row * 16 + lc] = fminf(fmaxf(16.f * sigf(v), 1.f), 16.f);
                } else {
                    v += sbmem[lc - 16];
                    g_m[row * 16 + (lc - 16)] = sigf(v);
                }
            }
            __syncthreads();

            if (tid < 128) {
                const float tau = g_t[tid];
                const float ml  = g_m[tid];
                const float hv  = t_h[tid];
                ring[(st & (RINGD - 1)) * 128 + tid] = 0.f;   // retire consumed slot
#pragma unroll
                for (int jp = 1; jp <= 16; ++jp) {
                    const int slot = (st + jp) & (RINGD - 1);
                    const float w = ml / (1.f + fabsf(tau - (float)jp));
                    ring[slot * 128 + tid] += w * hv;
                }
                const float h0n = ring[((st + 1) & (RINGD - 1)) * 128 + tid];
                const int row2 = tid >> 4, cl2 = tid & 15;
                g_h0[g][row2 * H + colbase + cl2] = h0n;
            }
        }
        GROUP_BAR();
    }
}

extern "C" void kernel_launch(void* const* d_in, const int* in_sizes, int n_in,
                              void* d_out, int out_size)
{
    // metadata order: x, lengths, [out_lengths scalar?], W_in, b_in, W_pass, b_pass,
    //                 W_tau, b_tau, W_mem, b_mem, W_out, b_out
    int wi = 2;
    if (n_in > 2 && in_sizes[2] == 1) wi = 3;   // skip scalar out_lengths if present

    const float* x       = (const float*)d_in[0];
    const int*   lengths = (const int*)  d_in[1];
    const float* W_in    = (const float*)d_in[wi + 0];
    const float* b_in    = (const float*)d_in[wi + 1];
    const float* W_pass  = (const float*)d_in[wi + 2];
    const float* b_pass  = (const float*)d_in[wi + 3];
    const float* W_tau   = (const float*)d_in[wi + 4];
    const float* b_tau   = (const float*)d_in[wi + 5];
    const float* W_mem   = (const float*)d_in[wi + 6];
    const float* b_mem   = (const float*)d_in[wi + 7];
    const float* W_out   = (const float*)d_in[wi + 8];
    const float* b_out   = (const float*)d_in[wi + 9];

    cudaFuncSetAttribute(delay_rnn_kernel,
                         cudaFuncAttributeMaxDynamicSharedMemorySize, SMEM_BYTES);

    delay_rnn_kernel<<<NCTAS, TPB, SMEM_BYTES>>>(
        x, lengths, W_in, b_in, W_pass, b_pass, W_tau, b_tau,
        W_mem, b_mem, W_out, b_out, (float*)d_out);
}

// round 5
// speedup vs baseline: 1.2599x; 1.2599x over previous
#include <cuda_runtime.h>
#include <cstddef>

// ---------------- problem constants ----------------
#define H       512
#define IDIM    128
#define KIN     640          // H + I
#define SEQ     256
#define OUTLEN  64
#define CDIM    64
#define BATCH   32
#define NSTEPS  (SEQ + OUTLEN)

// ---------------- partition ----------------
#define GROUPS  4                  // batch groups
#define PCOLS   32                 // column CTAs per group
#define BG      (BATCH / GROUPS)   // 8 batch rows per group
#define COLS    (H / PCOLS)        // 16 hidden cols per CTA
#define OUTC    (CDIM / PCOLS)     // 2 output cols per CTA
#define NCTAS   (GROUPS * PCOLS)   // 128
#define TPB     256
#define RINGD   32                 // ring depth (power of two >= 17)

// padded SMEM strides (floats) — multiples of 4 so double2/float4 stay 16B aligned
#define WS_IN   644          // KIN + 4
#define WS_H    516          // H + 4

// scratch for split-K partials (padded strides -> conflict-free)
#define SCR_FLOATS 4352      // max(128*33, 256*17)

// ---------------- SMEM layout (floats) ----------------
#define OFF_WIN    0
#define OFF_WPASS  (OFF_WIN   + COLS * WS_IN)
#define OFF_WTAU   (OFF_WPASS + COLS * WS_H)
#define OFF_WMEM   (OFF_WTAU  + COLS * WS_H)
#define OFF_WOUT   (OFF_WMEM  + COLS * WS_H)
#define OFF_BIAS   (OFF_WOUT  + OUTC * WS_H)      // 80 floats bias/len block
#define OFF_HS     (OFF_BIAS  + 80)               // BG * KIN staging
#define OFF_TH     (OFF_HS    + BG * KIN)         // 128 (mixed h)
#define OFF_THPRE  (OFF_TH    + 128)              // 128 (pre-mix h)
#define OFF_GT     (OFF_THPRE + 128)              // 128 (tau)
#define OFF_GM     (OFF_GT    + 128)              // 128 (mem gate)
#define OFF_SCR    (OFF_GM    + 128)              // SCR_FLOATS
#define OFF_RING   (OFF_SCR   + SCR_FLOATS)       // RINGD * 128
#define SMEM_FLOATS (OFF_RING + RINGD * 128)
#define SMEM_BYTES  (SMEM_FLOATS * 4)             // ~201 KB < 227 KB

// ---------------- global staging + flags ----------------
__device__ __align__(16) float g_h0  [GROUPS][BG * H];
__device__ __align__(16) float g_hpre[GROUPS][BG * H];
__device__ __align__(16) float g_hmix[GROUPS][BG * H];

// one monotonic flag per CTA, padded to a 128B line
__device__ unsigned g_flg[GROUPS * PCOLS * 32];

struct __align__(128) GroupBar { unsigned count; unsigned sense; unsigned pad[30]; };
__device__ GroupBar g_bar[GROUPS];

__device__ __forceinline__ float sigf(float z) { return 1.f / (1.f + __expf(-z)); }

__device__ __forceinline__ void st_rel(unsigned* a, unsigned v) {
    asm volatile("st.release.gpu.global.u32 [%0], %1;" :: "l"(a), "r"(v) : "memory");
}
__device__ __forceinline__ unsigned ld_acq(const unsigned* a) {
    unsigned v;
    asm volatile("ld.acquire.gpu.global.u32 %0, [%1];" : "=r"(v) : "l"(a) : "memory");
    return v;
}

// producer: data stores (weak) -> bar.sync -> release flag.
// hb chain: writer stores -hb(bar)-> tid0 release -sw-> consumer acquire -hb(bar)-> reads.
#define PUBLISH(val)                                                           \
    do {                                                                       \
        __syncthreads();                                                       \
        if (tid == 0) st_rel(&g_flg[(g * PCOLS + p) * 32], (unsigned)(val));   \
    } while (0)

#define WAIT_FLAGS(val)                                                        \
    do {                                                                       \
        if (tid < PCOLS) {                                                     \
            const unsigned* fp = &g_flg[(g * PCOLS + tid) * 32];               \
            while (ld_acq(fp) < (unsigned)(val)) { }                           \
        }                                                                      \
        __syncthreads();                                                       \
    } while (0)

// packed dual-FMA: acc(2xf32) += h(2xf32) * w(2xf32); operands loaded as double2
__device__ __forceinline__ void fma2pk(unsigned long long& acc, double h, double w)
{
    asm("fma.rn.f32x2 %0, %1, %2, %0;"
        : "+l"(acc)
        : "l"(__double_as_longlong(h)), "l"(__double_as_longlong(w)));
}

__device__ __forceinline__ float pk_sum(unsigned long long a)
{
    float lo = __uint_as_float((unsigned)(a & 0xffffffffu));
    float hi = __uint_as_float((unsigned)(a >> 32));
    return lo + hi;
}

__device__ __forceinline__ void fma16x2(const double2 hd[4], const double2 wd[4],
                                        unsigned long long acc[4][4])
{
#pragma unroll
    for (int r = 0; r < 4; ++r)
#pragma unroll
        for (int c = 0; c < 4; ++c) {
            fma2pk(acc[r][c], hd[r].x, wd[c].x);
            fma2pk(acc[r][c], hd[r].y, wd[c].y);
        }
}

// classic sense barrier — used ONCE at kernel end (guards flag reset)
#define GROUP_BAR_FINAL()                                                    \
    do {                                                                     \
        __threadfence();                                                     \
        __syncthreads();                                                     \
        if (tid == 0) {                                                      \
            unsigned ns = bsense ^ 1u;                                       \
            bsense = ns;                                                     \
            if (atomicAdd(&g_bar[g].count, 1u) == (unsigned)(PCOLS - 1)) {   \
                g_bar[g].count = 0u;                                         \
                __threadfence();                                             \
                atomicExch(&g_bar[g].sense, ns);                             \
            } else {                                                         \
                while (*(volatile unsigned*)&g_bar[g].sense != ns) { }       \
            }                                                                \
        }                                                                    \
        __syncthreads();                                                     \
    } while (0)

extern "C" __global__ void __launch_bounds__(TPB, 1)
delay_rnn_kernel(const float* __restrict__ x,       // [B, S, I]
                 const int*   __restrict__ lengths, // [B]
                 const float* __restrict__ W_in,    // [KIN, H]
                 const float* __restrict__ b_in,    // [H]
                 const float* __restrict__ W_pass,  // [H, H]
                 const float* __restrict__ b_pass,
                 const float* __restrict__ W_tau,
                 const float* __restrict__ b_tau,
                 const float* __restrict__ W_mem,
                 const float* __restrict__ b_mem,
                 const float* __restrict__ W_out,   // [H, C]
                 const float* __restrict__ b_out,   // [C]
                 float*       __restrict__ out)     // [B, OUTLEN, C]
{
    extern __shared__ float sm[];
    const int tid     = threadIdx.x;
    const int cta     = blockIdx.x;
    const int g       = cta >> 5;        // batch group
    const int p       = cta & 31;        // column partition
    const int b0      = g * BG;
    const int colbase = p * COLS;
    const int oc0     = p * OUTC;

    float* sWin   = sm + OFF_WIN;
    float* sWpass = sm + OFF_WPASS;
    float* sWtau  = sm + OFF_WTAU;
    float* sWmem  = sm + OFF_WMEM;
    float* sWout  = sm + OFF_WOUT;
    float* sbin   = sm + OFF_BIAS;        // 16
    float* sbpass = sbin + 16;            // 16
    float* sbtau  = sbpass + 16;          // 16
    float* sbmem  = sbtau + 16;           // 16
    float* sbout  = sbmem + 16;           // 4 (2 used)
    int*   slen   = (int*)(sbout + 4);    // 8
    float* h_s    = sm + OFF_HS;
    float* t_h    = sm + OFF_TH;
    float* t_hpre = sm + OFF_THPRE;
    float* g_t    = sm + OFF_GT;
    float* g_m    = sm + OFF_GM;
    float* scr    = sm + OFF_SCR;
    float* ring   = sm + OFF_RING;

    // ---- prologue: weights -> SMEM (transposed, padded) ----
    for (int idx = tid; idx < KIN * COLS; idx += TPB) {
        int k = idx >> 4, cl = idx & 15;
        sWin[cl * WS_IN + k] = W_in[k * H + colbase + cl];
    }
    for (int idx = tid; idx < H * COLS; idx += TPB) {
        int k = idx >> 4, cl = idx & 15;
        sWpass[cl * WS_H + k] = W_pass[k * H + colbase + cl];
        sWtau [cl * WS_H + k] = W_tau [k * H + colbase + cl];
        sWmem [cl * WS_H + k] = W_mem [k * H + colbase + cl];
    }
    for (int idx = tid; idx < H * OUTC; idx += TPB) {
        int k = idx >> 1, c = idx & 1;
        sWout[c * WS_H + k] = W_out[k * CDIM + oc0 + c];
    }
    if (tid < 16) {
        sbin[tid]   = b_in  [colbase + tid];
        sbpass[tid] = b_pass[colbase + tid];
        sbtau[tid]  = b_tau [colbase + tid];
        sbmem[tid]  = b_mem [colbase + tid];
    }
    if (tid < OUTC) sbout[tid] = b_out[oc0 + tid];
    if (tid < BG)   slen[tid]  = lengths[b0 + tid];
    for (int idx = tid; idx < RINGD * 128; idx += TPB) ring[idx] = 0.f;
    if (tid < 128) {  // initial h0 = 0
        int row = tid >> 4, cl = tid & 15;
        g_h0[g][row * H + colbase + cl] = 0.f;
    }

    unsigned bsense = 0;
    if (tid == 0) bsense = *(volatile unsigned*)&g_bar[g].sense;

    PUBLISH(1);    // initial h0 slice ready

    // tile coordinates (fixed per thread)
    const int sA  = tid & 31;             // split id, phases A/B (32-way)
    const int tlA = tid >> 5;             // tile id,  phases A/B (8 tiles)
    const int rA  = (tlA & 1) * 4;        // row base 0/4
    const int cA  = (tlA >> 1) * 4;       // col base 0/4/8/12

    const int sC  = tid & 15;             // split id, phase C (16-way)
    const int tlC = tid >> 4;             // tile id,  phase C (16 tiles)
    const int rC  = (tlC & 1) * 4;
    const int cC  = (tlC >> 1) * 4;       // col base 0..28 (32 logical cols)

    // paired-reduction coords (phases A/B): two threads per output element
    const int oR   = tid >> 1;            // output id 0..127
    const int hR   = tid & 1;             // half id
    const int rowR = oR >> 4, clR = oR & 15;

    for (int st = 0; st < NSTEPS; ++st) {
        const bool enc = (st < SEQ);
        const int  Kt  = enc ? KIN : H;

        // ================= Phase A: h_pre = [h0, x_t] @ W_in + b_in =================
        {
            if (enc) {   // x_t prefetch BEFORE the flag wait (independent data)
                int row = tid >> 5, iq = tid & 31;  // 8 rows x 32 f4
                float4 v = __ldg((const float4*)(x + ((size_t)(b0 + row) * SEQ + st) * IDIM) + iq);
                *((float4*)(h_s + row * KIN + H) + iq) = v;
            }
            WAIT_FLAGS(3 * st + 1);      // everyone's h0 slice published

            for (int i = tid; i < (BG * H) / 4; i += TPB) {
                int row = i >> 7, kq = i & 127;
                float4 v = __ldcg((const float4*)g_h0[g] + i);
                *((float4*)(h_s + row * KIN) + kq) = v;
            }
            __syncthreads();

            unsigned long long acc[4][4] = {};
            const int nj = Kt >> 7;                  // 5 (enc) or 4 (dec)
            for (int j = 0; j < nj; ++j) {
                const int k = sA * 4 + j * 128;      // strided split-K, contiguous per warp
                double2 hd[4], wd[4];
#pragma unroll
                for (int r = 0; r < 4; ++r)
                    hd[r] = *(const double2*)(h_s + (rA + r) * KIN + k);
#pragma unroll
                for (int c = 0; c < 4; ++c)
                    wd[c] = *(const double2*)(sWin + (cA + c) * WS_IN + k);
                fma16x2(hd, wd, acc);
            }
#pragma unroll
            for (int r = 0; r < 4; ++r)
#pragma unroll
                for (int c = 0; c < 4; ++c)
                    scr[((rA + r) * 16 + cA + c) * 33 + sA] = pk_sum(acc[r][c]);
            __syncthreads();

            {   // paired reduction: 256 threads, 16 partials each + shfl combine
                float v = 0.f;
#pragma unroll
                for (int s2 = 0; s2 < 16; ++s2) v += scr[oR * 33 + hR * 16 + s2];
                v += __shfl_xor_sync(0xffffffffu, v, 1);
                if (hR == 0) {
                    float hv = v + sbin[clR];
                    t_hpre[oR] = hv;
                    g_hpre[g][rowR * H + colbase + clR] = hv;
                }
            }
        }
        PUBLISH(3 * st + 2);             // h_pre slice ready (before decode epilogue)

        if (!enc) {
            // decode output: out = h0 @ W_out + b_out   (16-way split-K, h0 in h_s)
            __syncthreads();
            const int oo = tid >> 4, kp = tid & 15;     // oo: 8 rows x 2 cols
            const int row = oo >> 1, c = oo & 1;
            const float* hr = h_s + row * KIN + kp * 32;
            const float* wr = sWout + c * WS_H + kp * 32;
            float a = 0.f;
#pragma unroll
            for (int k = 0; k < 32; k += 4) {
                float4 h4 = *(const float4*)(hr + k);
                float4 w4 = *(const float4*)(wr + k);
                a = fmaf(h4.x, w4.x, a); a = fmaf(h4.y, w4.y, a);
                a = fmaf(h4.z, w4.z, a); a = fmaf(h4.w, w4.w, a);
            }
            scr[tid] = a;
            __syncthreads();
            if (tid < 16) {
                float s = 0.f;
#pragma unroll
                for (int j = 0; j < 16; ++j) s += scr[tid * 16 + j];
                const int row2 = tid >> 1, c2 = tid & 1;
                const int td = st - SEQ;
                out[((size_t)(b0 + row2) * OUTLEN + td) * CDIM + oc0 + c2] = s + sbout[c2];
            }
        }

        // ====== Phase B: p = h_pre @ W_pass + b_pass;  h = m*p + (1-m)*h_pre ======
        {
            WAIT_FLAGS(3 * st + 2);
            for (int i = tid; i < (BG * H) / 4; i += TPB) {
                int row = i >> 7, kq = i & 127;
                *((float4*)(h_s + row * KIN) + kq) = __ldcg((const float4*)g_hpre[g] + i);
            }
            __syncthreads();

            unsigned long long acc[4][4] = {};
#pragma unroll
            for (int j = 0; j < 4; ++j) {
                const int k = sA * 4 + j * 128;
                double2 hd[4], wd[4];
#pragma unroll
                for (int r = 0; r < 4; ++r)
                    hd[r] = *(const double2*)(h_s + (rA + r) * KIN + k);
#pragma unroll
                for (int c = 0; c < 4; ++c)
                    wd[c] = *(const double2*)(sWpass + (cA + c) * WS_H + k);
                fma16x2(hd, wd, acc);
            }
#pragma unroll
            for (int r = 0; r < 4; ++r)
#pragma unroll
                for (int c = 0; c < 4; ++c)
                    scr[((rA + r) * 16 + cA + c) * 33 + sA] = pk_sum(acc[r][c]);
            __syncthreads();

            {   // paired reduction + mask mixing
                float v = 0.f;
#pragma unroll
                for (int s2 = 0; s2 < 16; ++s2) v += scr[oR * 33 + hR * 16 + s2];
                v += __shfl_xor_sync(0xffffffffu, v, 1);
                if (hR == 0) {
                    float pv = v + sbpass[clR];
                    float hv;
                    if (enc) {
                        float m = (st < slen[rowR]) ? 1.f : 0.f;
                        hv = m * pv + (1.f - m) * t_hpre[oR];
                    } else {
                        hv = pv;
                    }
                    t_h[oR] = hv;
                    g_hmix[g][rowR * H + colbase + clR] = hv;
                }
            }
        }
        PUBLISH(3 * st + 3);

        // ====== Phase C: fused tau/mem gates (8 x 32 outputs) + ring update ======
        {
            WAIT_FLAGS(3 * st + 3);
            for (int i = tid; i < (BG * H) / 4; i += TPB) {
                int row = i >> 7, kq = i & 127;
                *((float4*)(h_s + row * KIN) + kq) = __ldcg((const float4*)g_hmix[g] + i);
            }
            __syncthreads();

            unsigned long long acc[4][4] = {};
#pragma unroll
            for (int j = 0; j < 8; ++j) {
                const int k = sC * 4 + j * 64;
                double2 hd[4], wd[4];
#pragma unroll
                for (int r = 0; r < 4; ++r)
                    hd[r] = *(const double2*)(h_s + (rC + r) * KIN + k);
#pragma unroll
                for (int c = 0; c < 4; ++c) {
                    const int lc = cC + c;    // 0..31 (tile stays on one side)
                    const float* wb = (lc < 16) ? (sWtau + lc * WS_H)
                                                : (sWmem + (lc - 16) * WS_H);
                    wd[c] = *(const double2*)(wb + k);
                }
                fma16x2(hd, wd, acc);
            }
#pragma unroll
            for (int r = 0; r < 4; ++r)
#pragma unroll
                for (int c = 0; c < 4; ++c)
                    scr[((rC + r) * 32 + cC + c) * 17 + sC] = pk_sum(acc[r][c]);
            __syncthreads();

            {   // reduction + gate nonlinearity (all 256 threads, one output each)
                const int row = tid >> 5, lc = tid & 31;
                float v = 0.f;
#pragma unroll 8
                for (int s2 = 0; s2 < 16; ++s2) v += scr[tid * 17 + s2];
                if (lc < 16) {
                    v += sbtau[lc];
                    g_t[row * 16 + lc] = fminf(fmaxf(16.f * sigf(v), 1.f), 16.f);
                } else {
                    v += sbmem[lc - 16];
                    g_m[row * 16 + (lc - 16)] = sigf(v);
                }
            }
            __syncthreads();

            if (tid < 128) {
                const float tau = g_t[tid];
                const float ml  = g_m[tid];
                const float hv  = t_h[tid];
                ring[(st & (RINGD - 1)) * 128 + tid] = 0.f;   // retire consumed slot
#pragma unroll
                for (int jp = 1; jp <= 16; ++jp) {
                    const int slot = (st + jp) & (RINGD - 1);
                    const float w = ml / (1.f + fabsf(tau - (float)jp));
                    ring[slot * 128 + tid] += w * hv;
                }
                const float h0n = ring[((st + 1) & (RINGD - 1)) * 128 + tid];
                const int row2 = tid >> 4, cl2 = tid & 15;
                g_h0[g][row2 * H + colbase + cl2] = h0n;
            }
        }
        PUBLISH(3 * st + 4);
    }

    // drain everyone, then reset flags for the next (graph-replayed) launch
    GROUP_BAR_FINAL();
    if (tid == 0) g_flg[(g * PCOLS + p) * 32] = 0u;
}

extern "C" void kernel_launch(void* const* d_in, const int* in_sizes, int n_in,
                              void* d_out, int out_size)
{
    // metadata order: x, lengths, [out_lengths scalar?], W_in, b_in, W_pass, b_pass,
    //                 W_tau, b_tau, W_mem, b_mem, W_out, b_out
    int wi = 2;
    if (n_in > 2 && in_sizes[2] == 1) wi = 3;   // skip scalar out_lengths if present

    const float* x       = (const float*)d_in[0];
    const int*   lengths = (const int*)  d_in[1];
    const float* W_in    = (const float*)d_in[wi + 0];
    const float* b_in    = (const float*)d_in[wi + 1];
    const float* W_pass  = (const float*)d_in[wi + 2];
    const float* b_pass  = (const float*)d_in[wi + 3];
    const float* W_tau   = (const float*)d_in[wi + 4];
    const float* b_tau   = (const float*)d_in[wi + 5];
    const float* W_mem   = (const float*)d_in[wi + 6];
    const float* b_mem   = (const float*)d_in[wi + 7];
    const float* W_out   = (const float*)d_in[wi + 8];
    const float* b_out   = (const float*)d_in[wi + 9];

    cudaFuncSetAttribute(delay_rnn_kernel,
                         cudaFuncAttributeMaxDynamicSharedMemorySize, SMEM_BYTES);

    delay_rnn_kernel<<<NCTAS, TPB, SMEM_BYTES>>>(
        x, lengths, W_in, b_in, W_pass, b_pass, W_tau, b_tau,
        W_mem, b_mem, W_out, b_out, (float*)d_out);
}